// round 10
// baseline (speedup 1.0000x reference)
#include <cuda_runtime.h>
#include <cuda_fp16.h>
#include <cstdint>

// ---------------------------------------------------------------------------
// ChannelMultiHeadAttention, fp32 in/out, fp16 tensor-core compute (m16n8k16).
//   energy = x A x^T + xu1 1^T + 1 xu2^T + c0,  A = Wq^T Wk
//   out    = att @ v + bv,  v = x @ Wv^T   (computed as vT C-frags)
// R10: x lives in 16 registers/lane (A-frag == B-frag word equivalence);
//      Y fused with energy (n-pair streaming); no per-warp x smem at all.
// ---------------------------------------------------------------------------

#define FULLMASK 0xffffffffu

// Packed B-frags of [A | u1 u2 | 0pad]: entry[(k0*4+tq)*84 + e] =
//   {h2(A[16k0+2tq][e], A[16k0+2tq+1][e]), h2(A[16k0+2tq+8][e], A[16k0+2tq+9][e])}
__device__ uint2  g_PA[16 * 84];
// Packed A-frags of Wv: entry[(mt*8+q)*36 + cp] =
//   {h2(Wv[16mt+q][2cp], [2cp+1]), h2(Wv[16mt+q+8][2cp], [2cp+1])}
__device__ uint2  g_PW[32 * 36];
__device__ __half g_wch[256];     // wc padded 16x16 fp16
__device__ float  g_Af[4096], g_u1f[64], g_u2f[64], g_c0[1];

__device__ __forceinline__ uint32_t h2u(float a, float b) {
    __half2 h = __floats2half2_rn(a, b);
    return *(uint32_t*)&h;
}

__device__ __forceinline__ void mma16(float* d, uint32_t a0, uint32_t a1, uint32_t a2,
                                      uint32_t a3, uint32_t b0, uint32_t b1) {
    asm("mma.sync.aligned.m16n8k16.row.col.f32.f16.f16.f32 "
        "{%0,%1,%2,%3}, {%4,%5,%6,%7}, {%8,%9}, {%0,%1,%2,%3};"
        : "+f"(d[0]), "+f"(d[1]), "+f"(d[2]), "+f"(d[3])
        : "r"(a0), "r"(a1), "r"(a2), "r"(a3), "r"(b0), "r"(b1));
}

// ---------------------------------------------------------------------------
__global__ void prep_kernel(const float* __restrict__ Wq, const float* __restrict__ bq,
                            const float* __restrict__ Wk, const float* __restrict__ bk,
                            const float* __restrict__ Wv, const float* __restrict__ wc) {
    __shared__ float sWq[4096], sWk[4096];
    int t = threadIdx.x;
    for (int i = t; i < 4096; i += 256) { sWq[i] = Wq[i]; sWk[i] = Wk[i]; }
    __syncthreads();
    for (int idx = t; idx < 4096; idx += 256) {
        int d = idx >> 6, e = idx & 63;
        float a = 0.f;
        #pragma unroll 8
        for (int f = 0; f < 64; f++) a += sWq[f * 64 + d] * sWk[f * 64 + e];
        g_Af[idx] = a;
    }
    if (t < 64) {
        float s1 = 0.f, s2 = 0.f;
        for (int f = 0; f < 64; f++) {
            s1 += sWq[f * 64 + t] * bk[f];
            s2 += sWk[f * 64 + t] * bq[f];
        }
        g_u1f[t] = s1; g_u2f[t] = s2;
    }
    if (t < 256) {
        int a = t >> 4, c = t & 15;
        float v = (a < 14 && c < 14) ? wc[a * 14 + c] : 0.f;
        g_wch[t] = __float2half_rn(v);
    }
    if (t == 0) {
        float c = 0.f;
        for (int f = 0; f < 64; f++) c += bq[f] * bk[f];
        g_c0[0] = c;
    }
    __syncthreads();

    // pack P_A (cols 0-63 = A, 64 = u1, 65 = u2, 66-71 = 0)
    for (int idx = t; idx < 16 * 72; idx += 256) {
        int kq = idx / 72, e = idx % 72;
        int k0 = kq >> 2, tq = kq & 3;
        int db = 16 * k0 + 2 * tq;
        float v0, v1, v2, v3;
        if (e < 64) {
            v0 = g_Af[db * 64 + e];       v1 = g_Af[(db + 1) * 64 + e];
            v2 = g_Af[(db + 8) * 64 + e]; v3 = g_Af[(db + 9) * 64 + e];
        } else if (e == 64) {
            v0 = g_u1f[db]; v1 = g_u1f[db + 1]; v2 = g_u1f[db + 8]; v3 = g_u1f[db + 9];
        } else if (e == 65) {
            v0 = g_u2f[db]; v1 = g_u2f[db + 1]; v2 = g_u2f[db + 8]; v3 = g_u2f[db + 9];
        } else { v0 = v1 = v2 = v3 = 0.f; }
        g_PA[kq * 84 + e] = make_uint2(h2u(v0, v1), h2u(v2, v3));
    }
    // pack P_W (A-operand of vT GEMM = Wv row-major)
    for (int idx = t; idx < 32 * 36; idx += 256) {
        int r = idx / 36, cp = idx % 36;
        int mt = r >> 3, q = r & 7;
        uint2 u = make_uint2(0u, 0u);
        if (cp < 32) {
            int e0 = 16 * mt + q;
            u.x = h2u(Wv[e0 * 64 + 2 * cp], Wv[e0 * 64 + 2 * cp + 1]);
            u.y = h2u(Wv[(e0 + 8) * 64 + 2 * cp], Wv[(e0 + 8) * 64 + 2 * cp + 1]);
        }
        g_PW[idx] = u;
    }
}

// ---------------------------------------------------------------------------
// Main: 1 warp = 1 pair, 8 warps/CTA, 8192 CTAs (exact).
// smem: PA 10752 + PW 9216 + wc 768 + bv 256 + ln 128 + NW*128 = 22144 B
// ---------------------------------------------------------------------------
static const int NW = 8;
static const int SMEM_BYTES = 10752 + 9216 + 768 + 256 + 128 + NW * 128;  // 22144

__global__ __launch_bounds__(32 * NW, 3)
void attn_kernel(const float* __restrict__ x, const float* __restrict__ bv,
                 const float* __restrict__ lng, const float* __restrict__ lnb,
                 float* __restrict__ out) {
    extern __shared__ __align__(16) unsigned char smraw[];
    uint2*  sPA  = (uint2*)smraw;                    // 16*84
    uint2*  sPW  = sPA + 16 * 84;                    // 32*36
    __half* swch = (__half*)(sPW + 32 * 36);         // 16 x 24
    float*  sbv  = (float*)(swch + 384);             // 64
    float*  slg  = sbv + 64;                         // 16
    float*  slb  = slg + 16;                         // 16
    float*  sxu  = slb + 16;                         // NW x 32

    const int t = threadIdx.x, w = t >> 5, l = t & 31;
    const int g = l >> 2, tg = l & 3;

    for (int i = t; i < 16 * 84; i += 32 * NW) sPA[i] = g_PA[i];
    for (int i = t; i < 32 * 36; i += 32 * NW) sPW[i] = g_PW[i];
    if (t < 256) swch[(t >> 4) * 24 + (t & 15)] = g_wch[t];
    if (t < 64) sbv[t] = bv[t];
    if (t < 16) {
        slg[t] = (t < 14) ? lng[t] : 0.f;
        slb[t] = (t < 14) ? lnb[t] : 0.f;
    }
    __syncthreads();

    const size_t pair = (size_t)blockIdx.x * NW + w;
    const float c0v = g_c0[0];
    float* sxu1 = sxu + w * 32;      // 16
    float* sxu2 = sxu1 + 16;         // 16

    // ---- x tile straight into registers as frag words ----
    // xA[k0][0]=row g      cols 16k0+2tg,+1   (A-frag a0 / energy-B nt0 b0 / vT b0)
    // xA[k0][1]=row g+8    same cols          (a1 / energy-B nt1 b0 / vT c0)
    // xA[k0][2]=row g      cols +8            (a2 / ... b1)
    // xA[k0][3]=row g+8    cols +8            (a3 / ... c1)   rows 14,15 = 0
    uint32_t xA[4][4];
    {
        const float2* xg2 = (const float2*)(x + pair * 896);
        #pragma unroll
        for (int k0 = 0; k0 < 4; k0++) {
            int cb = k0 * 8 + tg;
            float2 v00 = xg2[g * 32 + cb];
            float2 v01 = xg2[g * 32 + cb + 4];
            xA[k0][0] = h2u(v00.x, v00.y);
            xA[k0][2] = h2u(v01.x, v01.y);
            if (g < 6) {
                float2 v10 = xg2[(g + 8) * 32 + cb];
                float2 v11 = xg2[(g + 8) * 32 + cb + 4];
                xA[k0][1] = h2u(v10.x, v10.y);
                xA[k0][3] = h2u(v11.x, v11.y);
            } else { xA[k0][1] = 0u; xA[k0][3] = 0u; }
        }
    }

    // ---- fused Y + energy: stream Y n-pairs into energy k-steps ----
    float e[2][4] = {};
    #pragma unroll
    for (int np = 0; np < 4; np++) {
        float d0[4] = {}, d1[4] = {};
        #pragma unroll
        for (int k0 = 0; k0 < 4; k0++) {
            const uint2* pa = sPA + (k0 * 4 + tg) * 84 + g;
            uint2 bA = pa[(2 * np) * 8];
            uint2 bB = pa[(2 * np + 1) * 8];
            mma16(d0, xA[k0][0], xA[k0][1], xA[k0][2], xA[k0][3], bA.x, bA.y);
            mma16(d1, xA[k0][0], xA[k0][1], xA[k0][2], xA[k0][3], bB.x, bB.y);
        }
        // Y C-frags -> energy A-frags (lane-local identity packs)
        uint32_t a0 = h2u(d0[0], d0[1]);
        uint32_t a1 = h2u(d0[2], d0[3]);
        uint32_t a2 = h2u(d1[0], d1[1]);
        uint32_t a3 = h2u(d1[2], d1[3]);
        mma16(e[0], a0, a1, a2, a3, xA[np][0], xA[np][2]);
        mme_label:
        mma16(e[1], a0, a1, a2, a3, xA[np][1], xA[np][3]);
    }
    // ---- xu pass: Y cols 64-71 (u1/u2) ----
    {
        float d8[4] = {};
        #pragma unroll
        for (int k0 = 0; k0 < 4; k0++) {
            uint2 b = sPA[(k0 * 4 + tg) * 84 + 64 + g];
            mma16(d8, xA[k0][0], xA[k0][1], xA[k0][2], xA[k0][3], b.x, b.y);
        }
        if (tg == 0) {
            sxu1[g] = d8[0]; sxu2[g] = d8[1];
            sxu1[g + 8] = d8[2]; sxu2[g + 8] = d8[3];
        }
    }
    __syncwarp();

    // ---- add bias terms ----
    float et[2][4];
    {
        float xg0 = sxu1[g] + c0v, xg8 = sxu1[g + 8] + c0v;
        #pragma unroll
        for (int nt = 0; nt < 2; nt++) {
            int j0 = nt * 8 + 2 * tg;
            float u0 = sxu2[j0], u1v = sxu2[j0 + 1];
            et[nt][0] = e[nt][0] + xg0 + u0;
            et[nt][1] = e[nt][1] + xg0 + u1v;
            et[nt][2] = e[nt][2] + xg8 + u0;
            et[nt][3] = e[nt][3] + xg8 + u1v;
        }
    }

    // ---- mix = wc @ energy (2 MMAs); energy B-frags via quad shuffles ----
    float att0[2], att1[2], att2[2], att3[2];
    {
        uint32_t wa0 = *(const uint32_t*)(swch + g * 24 + 2 * tg);
        uint32_t wa1 = *(const uint32_t*)(swch + (g + 8) * 24 + 2 * tg);
        uint32_t wa2 = *(const uint32_t*)(swch + g * 24 + 2 * tg + 8);
        uint32_t wa3 = *(const uint32_t*)(swch + (g + 8) * 24 + 2 * tg + 8);
        const int s1 = 8 * tg + (g >> 1), s2 = s1 + 4;
        const bool podd = g & 1;
        float m[2][4] = {};
        #pragma unroll
        for (int nt = 0; nt < 2; nt++) {
            float f0 = __shfl_sync(FULLMASK, et[nt][0], s1);
            float f1 = __shfl_sync(FULLMASK, et[nt][1], s1);
            float f2 = __shfl_sync(FULLMASK, et[nt][2], s1);
            float f3 = __shfl_sync(FULLMASK, et[nt][3], s1);
            float h0 = __shfl_sync(FULLMASK, et[nt][0], s2);
            float h1 = __shfl_sync(FULLMASK, et[nt][1], s2);
            float h2v = __shfl_sync(FULLMASK, et[nt][2], s2);
            float h3 = __shfl_sync(FULLMASK, et[nt][3], s2);
            uint32_t b0 = h2u(podd ? f1 : f0, podd ? h1 : h0);
            uint32_t b1 = h2u(podd ? f3 : f2, podd ? h3 : h2v);
            mma16(m[nt], wa0, wa1, wa2, wa3, b0, b1);
        }
        // ---- LayerNorm + softmax in regs (quad reductions) ----
        const bool m3 = (tg == 3);   // cols 14,15
        float lg0 = slg[2 * tg], lg1 = slg[2 * tg + 1];
        float lg2 = slg[8 + 2 * tg], lg3 = slg[9 + 2 * tg];
        float lb0 = slb[2 * tg], lb1 = slb[2 * tg + 1];
        float lb2 = slb[8 + 2 * tg], lb3 = slb[9 + 2 * tg];
        #pragma unroll
        for (int rr = 0; rr < 2; rr++) {
            float v0 = m[0][2 * rr], v1 = m[0][2 * rr + 1];
            float v2 = m[1][2 * rr], v3 = m[1][2 * rr + 1];
            float s = v0 + v1 + (m3 ? 0.f : (v2 + v3));
            s += __shfl_xor_sync(FULLMASK, s, 1);
            s += __shfl_xor_sync(FULLMASK, s, 2);
            float mu = s * (1.f / 14.f);
            float d0 = v0 - mu, d1 = v1 - mu, d2 = v2 - mu, d3 = v3 - mu;
            float q = d0 * d0 + d1 * d1 + (m3 ? 0.f : (d2 * d2 + d3 * d3));
            q += __shfl_xor_sync(FULLMASK, q, 1);
            q += __shfl_xor_sync(FULLMASK, q, 2);
            float rsv = rsqrtf(q * (1.f / 14.f) + 1e-5f);
            float t0 = (d0 * rsv * lg0 + lb0) * 0.125f;
            float t1 = (d1 * rsv * lg1 + lb1) * 0.125f;
            float t2 = (d2 * rsv * lg2 + lb2) * 0.125f;
            float t3 = (d3 * rsv * lg3 + lb3) * 0.125f;
            float mx = fmaxf(fmaxf(t0, t1), m3 ? -1e30f : fmaxf(t2, t3));
            mx = fmaxf(mx, __shfl_xor_sync(FULLMASK, mx, 1));
            mx = fmaxf(mx, __shfl_xor_sync(FULLMASK, mx, 2));
            float e0 = __expf(t0 - mx), e1 = __expf(t1 - mx);
            float e2 = m3 ? 0.f : __expf(t2 - mx);
            float e3 = m3 ? 0.f : __expf(t3 - mx);
            float ss = e0 + e1 + e2 + e3;
            ss += __shfl_xor_sync(FULLMASK, ss, 1);
            ss += __shfl_xor_sync(FULLMASK, ss, 2);
            float inv = 1.f / ss;
            att0[rr] = e0 * inv; att1[rr] = e1 * inv;
            att2[rr] = e2 * inv; att3[rr] = e3 * inv;
        }
    }
    // att C-frag -> A-frag: lane-local identity packs
    uint32_t aa0 = h2u(att0[0], att1[0]);
    uint32_t aa1 = h2u(att0[1], att1[1]);
    uint32_t aa2 = h2u(att2[0], att3[0]);
    uint32_t aa3 = h2u(att2[1], att3[1]);

    // ---- vT = Wv-as-A @ x-as-B (x frags from regs), fused with out ----
    float* og = out + pair * 896;
    #pragma unroll
    for (int mt = 0; mt < 4; mt++) {
        float dv0[4] = {}, dv1[4] = {};
        #pragma unroll
        for (int k0 = 0; k0 < 4; k0++) {
            const uint2* pw = sPW + (mt * 8 + g) * 36 + 8 * k0 + tg;
            uint2 A01 = pw[0];
            uint2 A23 = pw[4];
            mma16(dv0, A01.x, A01.y, A23.x, A23.y, xA[k0][0], xA[k0][2]);
            mma16(dv1, A01.x, A01.y, A23.x, A23.y, xA[k0][1], xA[k0][3]);
        }
        // out columns 16mt..16mt+15: vT C-frags ARE the needed B-frags
        #pragma unroll
        for (int p = 0; p < 2; p++) {
            uint32_t b0 = h2u(dv0[2 * p], dv0[2 * p + 1]);
            uint32_t b1 = h2u(dv1[2 * p], dv1[2 * p + 1]);
            float od[4] = {};
            mma16(od, aa0, aa1, aa2, aa3, b0, b1);
            int cc = (2 * mt + p) * 8 + 2 * tg;
            float2 bb = *(const float2*)(sbv + cc);
            *(float2*)(og + g * 64 + cc) = make_float2(od[0] + bb.x, od[1] + bb.y);
            if (g < 6)
                *(float2*)(og + (g + 8) * 64 + cc) =
                    make_float2(od[2] + bb.x, od[3] + bb.y);
        }
    }
}

// ---------------------------------------------------------------------------
extern "C" void kernel_launch(void* const* d_in, const int* in_sizes, int n_in,
                              void* d_out, int out_size) {
    const float* x   = (const float*)d_in[0];
    const float* wc  = (const float*)d_in[1];
    const float* Wq  = (const float*)d_in[2];
    const float* bq  = (const float*)d_in[3];
    const float* Wk  = (const float*)d_in[4];
    const float* bk  = (const float*)d_in[5];
    const float* Wv  = (const float*)d_in[6];
    const float* bv  = (const float*)d_in[7];
    const float* lng = (const float*)d_in[8];
    const float* lnb = (const float*)d_in[9];
    float* out = (float*)d_out;

    cudaFuncSetAttribute(attn_kernel, cudaFuncAttributeMaxDynamicSharedMemorySize,
                         SMEM_BYTES);

    prep_kernel<<<1, 256>>>(Wq, bq, Wk, bk, Wv, wc);
    attn_kernel<<<8192, 32 * NW, SMEM_BYTES>>>(x, bv, lng, lnb, out);
}

// round 11
// speedup vs baseline: 1.0595x; 1.0595x over previous
#include <cuda_runtime.h>
#include <cuda_fp16.h>
#include <cstdint>

// ---------------------------------------------------------------------------
// ChannelMultiHeadAttention, fp32 in/out, fp16 tensor-core compute (m16n8k16).
//   energy = x A x^T + xu1 1^T + 1 xu2^T + c0,  A = Wq^T Wk
//   out    = att @ v + bv,  v = x @ Wv^T   (computed as vT C-frags)
// R11: x in registers (R10) + restored MMA ILP (2-wide np/mt fusion)
//      + 4 CTA/SM occupancy (64-reg cap).
// ---------------------------------------------------------------------------

#define FULLMASK 0xffffffffu

// Packed B-frags of [A | u1 u2 | 0pad]: entry[(k0*4+tq)*84 + e] =
//   {h2(A[16k0+2tq][e], A[16k0+2tq+1][e]), h2(A[16k0+2tq+8][e], A[16k0+2tq+9][e])}
__device__ uint2  g_PA[16 * 84];
// Packed A-frags of Wv: entry[(mt*8+q)*36 + cp] =
//   {h2(Wv[16mt+q][2cp], [2cp+1]), h2(Wv[16mt+q+8][2cp], [2cp+1])}
__device__ uint2  g_PW[32 * 36];
__device__ __half g_wch[256];     // wc padded 16x16 fp16
__device__ float  g_Af[4096], g_u1f[64], g_u2f[64], g_c0[1];

__device__ __forceinline__ uint32_t h2u(float a, float b) {
    __half2 h = __floats2half2_rn(a, b);
    return *(uint32_t*)&h;
}

__device__ __forceinline__ void mma16(float* d, uint32_t a0, uint32_t a1, uint32_t a2,
                                      uint32_t a3, uint32_t b0, uint32_t b1) {
    asm("mma.sync.aligned.m16n8k16.row.col.f32.f16.f16.f32 "
        "{%0,%1,%2,%3}, {%4,%5,%6,%7}, {%8,%9}, {%0,%1,%2,%3};"
        : "+f"(d[0]), "+f"(d[1]), "+f"(d[2]), "+f"(d[3])
        : "r"(a0), "r"(a1), "r"(a2), "r"(a3), "r"(b0), "r"(b1));
}

// ---------------------------------------------------------------------------
__global__ void prep_kernel(const float* __restrict__ Wq, const float* __restrict__ bq,
                            const float* __restrict__ Wk, const float* __restrict__ bk,
                            const float* __restrict__ Wv, const float* __restrict__ wc) {
    __shared__ float sWq[4096], sWk[4096];
    int t = threadIdx.x;
    for (int i = t; i < 4096; i += 256) { sWq[i] = Wq[i]; sWk[i] = Wk[i]; }
    __syncthreads();
    for (int idx = t; idx < 4096; idx += 256) {
        int d = idx >> 6, e = idx & 63;
        float a = 0.f;
        #pragma unroll 8
        for (int f = 0; f < 64; f++) a += sWq[f * 64 + d] * sWk[f * 64 + e];
        g_Af[idx] = a;
    }
    if (t < 64) {
        float s1 = 0.f, s2 = 0.f;
        for (int f = 0; f < 64; f++) {
            s1 += sWq[f * 64 + t] * bk[f];
            s2 += sWk[f * 64 + t] * bq[f];
        }
        g_u1f[t] = s1; g_u2f[t] = s2;
    }
    if (t < 256) {
        int a = t >> 4, c = t & 15;
        float v = (a < 14 && c < 14) ? wc[a * 14 + c] : 0.f;
        g_wch[t] = __float2half_rn(v);
    }
    if (t == 0) {
        float c = 0.f;
        for (int f = 0; f < 64; f++) c += bq[f] * bk[f];
        g_c0[0] = c;
    }
    __syncthreads();

    // pack P_A (cols 0-63 = A, 64 = u1, 65 = u2, 66-71 = 0)
    for (int idx = t; idx < 16 * 72; idx += 256) {
        int kq = idx / 72, e = idx % 72;
        int k0 = kq >> 2, tq = kq & 3;
        int db = 16 * k0 + 2 * tq;
        float v0, v1, v2, v3;
        if (e < 64) {
            v0 = g_Af[db * 64 + e];       v1 = g_Af[(db + 1) * 64 + e];
            v2 = g_Af[(db + 8) * 64 + e]; v3 = g_Af[(db + 9) * 64 + e];
        } else if (e == 64) {
            v0 = g_u1f[db]; v1 = g_u1f[db + 1]; v2 = g_u1f[db + 8]; v3 = g_u1f[db + 9];
        } else if (e == 65) {
            v0 = g_u2f[db]; v1 = g_u2f[db + 1]; v2 = g_u2f[db + 8]; v3 = g_u2f[db + 9];
        } else { v0 = v1 = v2 = v3 = 0.f; }
        g_PA[kq * 84 + e] = make_uint2(h2u(v0, v1), h2u(v2, v3));
    }
    // pack P_W (A-operand of vT GEMM = Wv row-major)
    for (int idx = t; idx < 32 * 36; idx += 256) {
        int r = idx / 36, cp = idx % 36;
        int mt = r >> 3, q = r & 7;
        uint2 u = make_uint2(0u, 0u);
        if (cp < 32) {
            int e0 = 16 * mt + q;
            u.x = h2u(Wv[e0 * 64 + 2 * cp], Wv[e0 * 64 + 2 * cp + 1]);
            u.y = h2u(Wv[(e0 + 8) * 64 + 2 * cp], Wv[(e0 + 8) * 64 + 2 * cp + 1]);
        }
        g_PW[idx] = u;
    }
}

// ---------------------------------------------------------------------------
// Main: 1 warp = 1 pair, 8 warps/CTA, 8192 CTAs (exact), 4 CTA/SM.
// smem: PA 10752 + PW 9216 + wc 768 + bv 256 + ln 128 + NW*128 = 22144 B
// ---------------------------------------------------------------------------
static const int NW = 8;
static const int SMEM_BYTES = 10752 + 9216 + 768 + 256 + 128 + NW * 128;  // 22144

__global__ __launch_bounds__(32 * NW, 4)
void attn_kernel(const float* __restrict__ x, const float* __restrict__ bv,
                 const float* __restrict__ lng, const float* __restrict__ lnb,
                 float* __restrict__ out) {
    extern __shared__ __align__(16) unsigned char smraw[];
    uint2*  sPA  = (uint2*)smraw;                    // 16*84
    uint2*  sPW  = sPA + 16 * 84;                    // 32*36
    __half* swch = (__half*)(sPW + 32 * 36);         // 16 x 24
    float*  sbv  = (float*)(swch + 384);             // 64
    float*  slg  = sbv + 64;                         // 16
    float*  slb  = slg + 16;                         // 16
    float*  sxu  = slb + 16;                         // NW x 32

    const int t = threadIdx.x, w = t >> 5, l = t & 31;
    const int g = l >> 2, tg = l & 3;

    for (int i = t; i < 16 * 84; i += 32 * NW) sPA[i] = g_PA[i];
    for (int i = t; i < 32 * 36; i += 32 * NW) sPW[i] = g_PW[i];
    if (t < 256) swch[(t >> 4) * 24 + (t & 15)] = g_wch[t];
    if (t < 64) sbv[t] = bv[t];
    if (t < 16) {
        slg[t] = (t < 14) ? lng[t] : 0.f;
        slb[t] = (t < 14) ? lnb[t] : 0.f;
    }
    __syncthreads();

    const size_t pair = (size_t)blockIdx.x * NW + w;
    const float c0v = g_c0[0];
    float* sxu1 = sxu + w * 32;      // 16
    float* sxu2 = sxu1 + 16;         // 16

    // ---- x tile straight into registers as frag words ----
    // xA[k0][0]=row g      cols 16k0+2tg,+1   (A-frag a0 / energy-B nt0 b0 / vT b0)
    // xA[k0][1]=row g+8    same cols          (a1 / energy-B nt1 b0 / vT c0)
    // xA[k0][2]=row g      cols +8            (a2 / ... b1)
    // xA[k0][3]=row g+8    cols +8            (a3 / ... c1)   rows 14,15 = 0
    uint32_t xA[4][4];
    {
        const float2* xg2 = (const float2*)(x + pair * 896);
        #pragma unroll
        for (int k0 = 0; k0 < 4; k0++) {
            int cb = k0 * 8 + tg;
            float2 v00 = xg2[g * 32 + cb];
            float2 v01 = xg2[g * 32 + cb + 4];
            xA[k0][0] = h2u(v00.x, v00.y);
            xA[k0][2] = h2u(v01.x, v01.y);
            if (g < 6) {
                float2 v10 = xg2[(g + 8) * 32 + cb];
                float2 v11 = xg2[(g + 8) * 32 + cb + 4];
                xA[k0][1] = h2u(v10.x, v10.y);
                xA[k0][3] = h2u(v11.x, v11.y);
            } else { xA[k0][1] = 0u; xA[k0][3] = 0u; }
        }
    }

    // ---- fused Y + energy, 2-wide in np (4 dY chains + 2 e chains) ----
    float e[2][4] = {};
    #pragma unroll
    for (int npp = 0; npp < 2; npp++) {
        float d0[4] = {}, d1[4] = {}, d2[4] = {}, d3[4] = {};
        #pragma unroll
        for (int k0 = 0; k0 < 4; k0++) {
            const uint2* pa = sPA + (k0 * 4 + tg) * 84 + g;
            uint2 bA = pa[(4 * npp) * 8];
            uint2 bB = pa[(4 * npp + 1) * 8];
            uint2 bC = pa[(4 * npp + 2) * 8];
            uint2 bD = pa[(4 * npp + 3) * 8];
            mma16(d0, xA[k0][0], xA[k0][1], xA[k0][2], xA[k0][3], bA.x, bA.y);
            mma16(d1, xA[k0][0], xA[k0][1], xA[k0][2], xA[k0][3], bB.x, bB.y);
            mma16(d2, xA[k0][0], xA[k0][1], xA[k0][2], xA[k0][3], bC.x, bC.y);
            mma16(d3, xA[k0][0], xA[k0][1], xA[k0][2], xA[k0][3], bD.x, bD.y);
        }
        // Y C-frags -> energy A-frags (lane-local identity packs)
        {
            const int np = 2 * npp;
            uint32_t a0 = h2u(d0[0], d0[1]);
            uint32_t a1 = h2u(d0[2], d0[3]);
            uint32_t a2 = h2u(d1[0], d1[1]);
            uint32_t a3 = h2u(d1[2], d1[3]);
            uint32_t c0 = h2u(d2[0], d2[1]);
            uint32_t c1 = h2u(d2[2], d2[3]);
            uint32_t c2 = h2u(d3[0], d3[1]);
            uint32_t c3 = h2u(d3[2], d3[3]);
            mma16(e[0], a0, a1, a2, a3, xA[np][0], xA[np][2]);
            mma16(e[1], a0, a1, a2, a3, xA[np][1], xA[np][3]);
            mma16(e[0], c0, c1, c2, c3, xA[np + 1][0], xA[np + 1][2]);
            mma16(e[1], c0, c1, c2, c3, xA[np + 1][1], xA[np + 1][3]);
        }
    }
    // ---- xu pass: Y cols 64-71 (u1/u2) ----
    {
        float d8[4] = {};
        #pragma unroll
        for (int k0 = 0; k0 < 4; k0++) {
            uint2 b = sPA[(k0 * 4 + tg) * 84 + 64 + g];
            mma16(d8, xA[k0][0], xA[k0][1], xA[k0][2], xA[k0][3], b.x, b.y);
        }
        if (tg == 0) {
            sxu1[g] = d8[0]; sxu2[g] = d8[1];
            sxu1[g + 8] = d8[2]; sxu2[g + 8] = d8[3];
        }
    }
    __syncwarp();

    // ---- add bias terms ----
    float et[2][4];
    {
        float xg0 = sxu1[g] + c0v, xg8 = sxu1[g + 8] + c0v;
        #pragma unroll
        for (int nt = 0; nt < 2; nt++) {
            int j0 = nt * 8 + 2 * tg;
            float u0 = sxu2[j0], u1v = sxu2[j0 + 1];
            et[nt][0] = e[nt][0] + xg0 + u0;
            et[nt][1] = e[nt][1] + xg0 + u1v;
            et[nt][2] = e[nt][2] + xg8 + u0;
            et[nt][3] = e[nt][3] + xg8 + u1v;
        }
    }

    // ---- mix = wc @ energy (2 MMAs); energy B-frags via quad shuffles ----
    float att0[2], att1[2], att2[2], att3[2];
    {
        uint32_t wa0 = *(const uint32_t*)(swch + g * 24 + 2 * tg);
        uint32_t wa1 = *(const uint32_t*)(swch + (g + 8) * 24 + 2 * tg);
        uint32_t wa2 = *(const uint32_t*)(swch + g * 24 + 2 * tg + 8);
        uint32_t wa3 = *(const uint32_t*)(swch + (g + 8) * 24 + 2 * tg + 8);
        const int s1 = 8 * tg + (g >> 1), s2 = s1 + 4;
        const bool podd = g & 1;
        float m[2][4] = {};
        #pragma unroll
        for (int nt = 0; nt < 2; nt++) {
            float f0 = __shfl_sync(FULLMASK, et[nt][0], s1);
            float f1 = __shfl_sync(FULLMASK, et[nt][1], s1);
            float f2 = __shfl_sync(FULLMASK, et[nt][2], s1);
            float f3 = __shfl_sync(FULLMASK, et[nt][3], s1);
            float h0 = __shfl_sync(FULLMASK, et[nt][0], s2);
            float h1 = __shfl_sync(FULLMASK, et[nt][1], s2);
            float h2v = __shfl_sync(FULLMASK, et[nt][2], s2);
            float h3 = __shfl_sync(FULLMASK, et[nt][3], s2);
            uint32_t b0 = h2u(podd ? f1 : f0, podd ? h1 : h0);
            uint32_t b1 = h2u(podd ? f3 : f2, podd ? h3 : h2v);
            mma16(m[nt], wa0, wa1, wa2, wa3, b0, b1);
        }
        // ---- LayerNorm + softmax in regs (quad reductions) ----
        const bool m3 = (tg == 3);   // cols 14,15
        float lg0 = slg[2 * tg], lg1 = slg[2 * tg + 1];
        float lg2 = slg[8 + 2 * tg], lg3 = slg[9 + 2 * tg];
        float lb0 = slb[2 * tg], lb1 = slb[2 * tg + 1];
        float lb2 = slb[8 + 2 * tg], lb3 = slb[9 + 2 * tg];
        #pragma unroll
        for (int rr = 0; rr < 2; rr++) {
            float v0 = m[0][2 * rr], v1 = m[0][2 * rr + 1];
            float v2 = m[1][2 * rr], v3 = m[1][2 * rr + 1];
            float s = v0 + v1 + (m3 ? 0.f : (v2 + v3));
            s += __shfl_xor_sync(FULLMASK, s, 1);
            s += __shfl_xor_sync(FULLMASK, s, 2);
            float mu = s * (1.f / 14.f);
            float d0 = v0 - mu, d1 = v1 - mu, d2 = v2 - mu, d3 = v3 - mu;
            float q = d0 * d0 + d1 * d1 + (m3 ? 0.f : (d2 * d2 + d3 * d3));
            q += __shfl_xor_sync(FULLMASK, q, 1);
            q += __shfl_xor_sync(FULLMASK, q, 2);
            float rsv = rsqrtf(q * (1.f / 14.f) + 1e-5f);
            float t0 = (d0 * rsv * lg0 + lb0) * 0.125f;
            float t1 = (d1 * rsv * lg1 + lb1) * 0.125f;
            float t2 = (d2 * rsv * lg2 + lb2) * 0.125f;
            float t3 = (d3 * rsv * lg3 + lb3) * 0.125f;
            float mx = fmaxf(fmaxf(t0, t1), m3 ? -1e30f : fmaxf(t2, t3));
            mx = fmaxf(mx, __shfl_xor_sync(FULLMASK, mx, 1));
            mx = fmaxf(mx, __shfl_xor_sync(FULLMASK, mx, 2));
            float e0 = __expf(t0 - mx), e1 = __expf(t1 - mx);
            float e2 = m3 ? 0.f : __expf(t2 - mx);
            float e3 = m3 ? 0.f : __expf(t3 - mx);
            float ss = e0 + e1 + e2 + e3;
            ss += __shfl_xor_sync(FULLMASK, ss, 1);
            ss += __shfl_xor_sync(FULLMASK, ss, 2);
            float inv = 1.f / ss;
            att0[rr] = e0 * inv; att1[rr] = e1 * inv;
            att2[rr] = e2 * inv; att3[rr] = e3 * inv;
        }
    }
    // att C-frag -> A-frag: lane-local identity packs
    uint32_t aa0 = h2u(att0[0], att1[0]);
    uint32_t aa1 = h2u(att0[1], att1[1]);
    uint32_t aa2 = h2u(att2[0], att3[0]);
    uint32_t aa3 = h2u(att2[1], att3[1]);

    // ---- vT = Wv-as-A @ x-as-B, fused with out, 2-wide in mt (4 dv chains) ----
    float* og = out + pair * 896;
    #pragma unroll
    for (int mtp = 0; mtp < 2; mtp++) {
        float dv[2][2][4] = {};   // [mt2][row-half]
        #pragma unroll
        for (int k0 = 0; k0 < 4; k0++) {
            #pragma unroll
            for (int mt2 = 0; mt2 < 2; mt2++) {
                const uint2* pw = sPW + ((2 * mtp + mt2) * 8 + g) * 36 + 8 * k0 + tg;
                uint2 A01 = pw[0];
                uint2 A23 = pw[4];
                mma16(dv[mt2][0], A01.x, A01.y, A23.x, A23.y, xA[k0][0], xA[k0][2]);
                mma16(dv[mt2][1], A01.x, A01.y, A23.x, A23.y, xA[k0][1], xA[k0][3]);
            }
        }
        // out columns: vT C-frags ARE the needed B-frags
        #pragma unroll
        for (int mt2 = 0; mt2 < 2; mt2++) {
            #pragma unroll
            for (int p = 0; p < 2; p++) {
                uint32_t b0 = h2u(dv[mt2][0][2 * p], dv[mt2][0][2 * p + 1]);
                uint32_t b1 = h2u(dv[mt2][1][2 * p], dv[mt2][1][2 * p + 1]);
                float od[4] = {};
                mma16(od, aa0, aa1, aa2, aa3, b0, b1);
                int cc = (2 * (2 * mtp + mt2) + p) * 8 + 2 * tg;
                float2 bb = *(const float2*)(sbv + cc);
                *(float2*)(og + g * 64 + cc) = make_float2(od[0] + bb.x, od[1] + bb.y);
                if (g < 6)
                    *(float2*)(og + (g + 8) * 64 + cc) =
                        make_float2(od[2] + bb.x, od[3] + bb.y);
            }
        }
    }
}

// ---------------------------------------------------------------------------
extern "C" void kernel_launch(void* const* d_in, const int* in_sizes, int n_in,
                              void* d_out, int out_size) {
    const float* x   = (const float*)d_in[0];
    const float* wc  = (const float*)d_in[1];
    const float* Wq  = (const float*)d_in[2];
    const float* bq  = (const float*)d_in[3];
    const float* Wk  = (const float*)d_in[4];
    const float* bk  = (const float*)d_in[5];
    const float* Wv  = (const float*)d_in[6];
    const float* bv  = (const float*)d_in[7];
    const float* lng = (const float*)d_in[8];
    const float* lnb = (const float*)d_in[9];
    float* out = (float*)d_out;

    cudaFuncSetAttribute(attn_kernel, cudaFuncAttributeMaxDynamicSharedMemorySize,
                         SMEM_BYTES);

    prep_kernel<<<1, 256>>>(Wq, bq, Wk, bk, Wv, wc);
    attn_kernel<<<8192, 32 * NW, SMEM_BYTES>>>(x, bv, lng, lnb, out);
}